// round 16
// baseline (speedup 1.0000x reference)
#include <cuda_runtime.h>
#include <cuda_fp16.h>
#include <cstdint>

#define NTHREADS 384
#define T        180
#define GRID_P   304
#define MAXN     2097152

typedef unsigned int u32;

// ---- W plane element offsets (fp16 elems) ----
#define PW2 0          // [5][40][40]  = 8000
#define PW3 8000       // [80][56]     = 4480
#define PW4 12480      // [40][84]     = 3360
#define PW5 15840      // [3][24][56]  = 4032
#define PLANE_ELEMS 19872

// ---- smem byte offsets ----
#define OWHI 0
#define OSC  (PLANE_ELEMS*2)            // 39744 (f32 scalars)
#define SW1 0
#define SB1 100
#define SB2 120
#define SB3 160
#define SB4 240
#define SB5 280      // 24 (20 real + 4 zero)
#define SW6 304      // 24 (20 real + 4 zero)
#define SB6 328
#define OBA 41472                       // bufA: 192*176 = 33792 B (y1/y3)
#define OBB (OBA+33792)                 // 75264  bufB: 192*112 = 21504 B (y2/y4)
#define ODIF (OBB+21504)                // 96768 (196 f32 + guard)
#define SMEM_BYTES (ODIF + 1024)        // 97792  -> 2 CTAs/SM

__device__ float g_bm[MAXN];

// ---------------- helpers ----------------
__device__ __forceinline__ u32 sm_u32(const void* p) {
    u32 a;
    asm("{ .reg .u64 t; cvta.to.shared.u64 t, %1; cvt.u32.u64 %0, t; }" : "=r"(a) : "l"(p));
    return a;
}
__device__ __forceinline__ void ldm4(u32 addr, u32& a0, u32& a1, u32& a2, u32& a3) {
    asm volatile("ldmatrix.sync.aligned.m8n8.x4.shared.b16 {%0,%1,%2,%3},[%4];"
                 : "=r"(a0), "=r"(a1), "=r"(a2), "=r"(a3) : "r"(addr));
}
__device__ __forceinline__ u32 lds32(u32 a) {
    u32 v; asm volatile("ld.shared.u32 %0,[%1];" : "=r"(v) : "r"(a)); return v;
}
__device__ __forceinline__ void sts32(u32 a, u32 v) {
    asm volatile("st.shared.u32 [%0],%1;" :: "r"(a), "r"(v));
}
__device__ __forceinline__ void mma16816(float* d, u32 a0, u32 a1, u32 a2, u32 a3, u32 b0, u32 b1) {
    asm volatile("mma.sync.aligned.m16n8k16.row.col.f32.f16.f16.f32 "
                 "{%0,%1,%2,%3},{%4,%5,%6,%7},{%8,%9},{%0,%1,%2,%3};"
                 : "+f"(d[0]), "+f"(d[1]), "+f"(d[2]), "+f"(d[3])
                 : "r"(a0), "r"(a1), "r"(a2), "r"(a3), "r"(b0), "r"(b1));
}
__device__ __forceinline__ float elu1(float x) {
    float e = __expf(x) - 1.0f;
    return x > 0.0f ? x : e;
}
// packed half2 elu: r = x>0 ? x : exp(min(x,0))-1   (min avoids inf-inf NaN)
__device__ __forceinline__ u32 elu2_pack(float v0, float v1) {
    __half2 xx = __floats2half2_rn(v0, v1);
    __half2 z = __float2half2_rn(0.f);
    __half2 one = __float2half2_rn(1.f);
    __half2 ex = __hsub2(h2exp(__hmin2(xx, z)), one);
    __half2 m = __hgt2(xx, z);                    // 1.0 / 0.0
    __half2 r = __hfma2(m, __hsub2(xx, ex), ex);
    u32 w; *(__half2*)&w = r; return w;
}

// ---------------- MMA conv layer (single-term fp16, half2-elu epilogue) ----------------
template<int TAPS, int PAD, int KC, int NT, int KP, int NR, int WOFS, int BOFS, int RLO, int RHI>
__device__ __forceinline__ void mma_layer(u32 smb, u32 src, int RSsrc,
                                          u32 dst, int RSdst,
                                          const float* sc, int warp, int lane, int g0, int N)
{
    float acc[NT][4];
    #pragma unroll
    for (int i = 0; i < NT; i++) { acc[i][0] = acc[i][1] = acc[i][2] = acc[i][3] = 0.f; }
    const int m0 = warp * 16;
    const int r = lane & 15, half = lane >> 4;
    const int c = lane & 3, nrow = lane >> 2;
    const u32 wB = smb + OWHI;

    #pragma unroll
    for (int t = 0; t < TAPS; t++) {
        #pragma unroll
        for (int kc = 0; kc < KC; kc++) {
            u32 aad = src + (u32)((m0 + r + t - PAD) * RSsrc) + kc * 32 + half * 16;
            u32 h0, h1, h2, h3;
            ldm4(aad, h0, h1, h2, h3);
            #pragma unroll
            for (int nt = 0; nt < NT; nt++) {
                int n = nt * 8 + nrow;
                u32 wo = wB + (u32)((WOFS + (t * NR + n) * KP + kc * 16 + 2 * c) * 2);
                u32 bh0 = lds32(wo), bh1 = lds32(wo + 16);
                mma16816(acc[nt], h0, h1, h2, h3, bh0, bh1);
            }
        }
    }
    // epilogue: bias + half2 elu + kill + store
    #pragma unroll
    for (int nt = 0; nt < NT; nt++) {
        int nb = nt * 8 + 2 * c;
        float b0f = sc[BOFS + nb], b1f = sc[BOFS + nb + 1];
        #pragma unroll
        for (int j = 0; j < 2; j++) {
            int row = m0 + nrow + 8 * j;
            int p = g0 + row - 6;
            bool kill = (row < RLO) | (row >= RHI) | (p < 0) | (p >= N);
            u32 word = elu2_pack(acc[nt][2 * j] + b0f, acc[nt][2 * j + 1] + b1f);
            if (kill) word = 0u;
            sts32(dst + (u32)(row * RSdst + nb * 2), word);
        }
    }
}

// ---------------- L5 + L6 fused: 40->20 k3 pad1, then 20->1 sigmoid+0.1 ----------------
__device__ __forceinline__ void mma_layer5_l6(u32 smb, u32 src,
                                              const float* sc, int warp, int lane, int g0, int N)
{
    float acc[3][4];
    #pragma unroll
    for (int i = 0; i < 3; i++) { acc[i][0] = acc[i][1] = acc[i][2] = acc[i][3] = 0.f; }
    const int m0 = warp * 16;
    const int r = lane & 15, half = lane >> 4;
    const int c = lane & 3, nrow = lane >> 2;
    const u32 wB = smb + OWHI;

    #pragma unroll
    for (int t = 0; t < 3; t++) {
        #pragma unroll
        for (int kc = 0; kc < 3; kc++) {
            u32 aad = src + (u32)((m0 + r + t - 1) * 112) + kc * 32 + half * 16;
            u32 h0, h1, h2, h3;
            ldm4(aad, h0, h1, h2, h3);
            #pragma unroll
            for (int nt = 0; nt < 3; nt++) {
                int n = nt * 8 + nrow;
                u32 wo = wB + (u32)((PW5 + (t * 24 + n) * 56 + kc * 16 + 2 * c) * 2);
                u32 bh0 = lds32(wo), bh1 = lds32(wo + 16);
                mma16816(acc[nt], h0, h1, h2, h3, bh0, bh1);
            }
        }
    }
    // fused epilogue: elu (f32) -> w6 dot partial -> butterfly over c -> sigmoid -> g_bm
    float part0 = 0.f, part1 = 0.f;
    #pragma unroll
    for (int nt = 0; nt < 3; nt++) {
        int nb = nt * 8 + 2 * c;
        float b0f = sc[SB5 + nb], b1f = sc[SB5 + nb + 1];
        float w0 = sc[SW6 + nb], w1 = sc[SW6 + nb + 1];
        part0 += w0 * elu1(acc[nt][0] + b0f) + w1 * elu1(acc[nt][1] + b1f);
        part1 += w0 * elu1(acc[nt][2] + b0f) + w1 * elu1(acc[nt][3] + b1f);
    }
    part0 += __shfl_xor_sync(0xffffffffu, part0, 1);
    part0 += __shfl_xor_sync(0xffffffffu, part0, 2);
    part1 += __shfl_xor_sync(0xffffffffu, part1, 1);
    part1 += __shfl_xor_sync(0xffffffffu, part1, 2);
    if (c == 0) {
        float b6v = sc[SB6];
        #pragma unroll
        for (int j = 0; j < 2; j++) {
            int row = m0 + nrow + 8 * j;
            int p = g0 + row - 6;
            if (row >= 6 && row < 186 && p < N) {
                float a = (j == 0 ? part0 : part1) + b6v;
                g_bm[p] = 1.f / (1.f + __expf(-a)) + 0.1f;
            }
        }
    }
}

__global__ __launch_bounds__(NTHREADS, 2)
void cnn_kernel(const float* __restrict__ uu,
                const float* __restrict__ w1, const float* __restrict__ b1,
                const float* __restrict__ w2, const float* __restrict__ b2,
                const float* __restrict__ w3, const float* __restrict__ b3,
                const float* __restrict__ w4, const float* __restrict__ b4,
                const float* __restrict__ w5, const float* __restrict__ b5,
                const float* __restrict__ w6, const float* __restrict__ b6,
                int N, int nTiles)
{
    extern __shared__ unsigned char sm[];
    const int tid = threadIdx.x, lane = tid & 31, warp = tid >> 5;
    const u32 smb = sm_u32(sm);
    float* sc = (float*)(sm + OSC);
    __half* WH = (__half*)(sm + OWHI);
    float* dif = (float*)(sm + ODIF);
    __half* bA = (__half*)(sm + OBA);

    // ---- scalars ----
    for (int i = tid; i < 100; i += NTHREADS) { int co = i / 5, t = i % 5; sc[SW1 + t * 20 + co] = w1[i]; }
    for (int i = tid; i < 20; i += NTHREADS) sc[SB1 + i] = b1[i];
    for (int i = tid; i < 40; i += NTHREADS) sc[SB2 + i] = b2[i];
    for (int i = tid; i < 80; i += NTHREADS) sc[SB3 + i] = b3[i];
    for (int i = tid; i < 40; i += NTHREADS) sc[SB4 + i] = b4[i];
    for (int i = tid; i < 24; i += NTHREADS) sc[SB5 + i] = (i < 20) ? b5[i] : 0.f;
    for (int i = tid; i < 24; i += NTHREADS) sc[SW6 + i] = (i < 20) ? w6[i] : 0.f;
    if (tid == 0) sc[SB6] = b6[0];

    // ---- weight planes (fp16), zero-padded ----
    #define PUTW(idx, wv) do { WH[idx] = __float2half_rn(wv); } while (0)
    for (int i = tid; i < 8000; i += NTHREADS) {         // W2 [5][40][40]
        int t = i / 1600, rr = i % 1600, n = rr / 40, ci = rr % 40;
        PUTW(PW2 + i, ci < 20 ? w2[(n * 20 + ci) * 5 + t] : 0.f);
    }
    for (int i = tid; i < 4480; i += NTHREADS) {         // W3 [80][56]
        int n = i / 56, ci = i % 56;
        PUTW(PW3 + i, ci < 40 ? w3[n * 40 + ci] : 0.f);
    }
    for (int i = tid; i < 3360; i += NTHREADS) {         // W4 [40][84]
        int n = i / 84, ci = i % 84;
        PUTW(PW4 + i, ci < 80 ? w4[n * 80 + ci] : 0.f);
    }
    for (int i = tid; i < 4032; i += NTHREADS) {         // W5 [3][24][56]
        int t = i / 1344, rr = i % 1344, n = rr / 56, ci = rr % 56;
        PUTW(PW5 + i, (n < 20 && ci < 40) ? w5[(n * 40 + ci) * 3 + t] : 0.f);
    }
    // zero activation buffers (once; padded cols stay finite/zero)
    {
        uint4* z = (uint4*)(sm + OBA);
        const int cnt = (33792 + 21504) / 16;
        for (int i = tid; i < cnt; i += NTHREADS) z[i] = make_uint4(0, 0, 0, 0);
    }
    __syncthreads();

    const u32 BA = smb + OBA, BB = smb + OBB;

    // ---- prefetch uu for first tile ----
    float pf0 = 0.f, pf1 = 0.f;
    {
        int gd = blockIdx.x * T + tid - 8;
        if (tid < 196 && blockIdx.x < nTiles) {
            int i0 = min(max(gd - 1, 0), N - 1);
            int i1 = min(max(gd + 1, 0), N - 1);
            pf0 = __ldg(&uu[i0]);
            pf1 = __ldg(&uu[i1]);
        }
    }

    for (int tile = blockIdx.x; tile < nTiles; tile += GRID_P) {
        const int g0 = tile * T;

        // ---- dif from prefetched regs: idx 0..195 <-> lp = idx-8 ----
        if (tid < 196) {
            int gd = g0 + tid - 8;
            float v = 0.f;
            if (gd >= 0 && gd < N) {
                float scale = (gd == 0 || gd == N - 1) ? 1.f : 0.5f;
                v = scale * (pf1 - pf0);
            }
            dif[tid] = v;
        }
        __syncthreads();   // also orders prev-tile L5 reads before new L1/L2 writes

        // ---- L1 scalar: 1->20 k5 pad2; row = lp+6, valid rows [2,190) ----
        for (int i = tid; i < 3840; i += NTHREADS) {
            int row = i % 192, co = i / 192;
            float a = sc[SB1 + co];
            #pragma unroll
            for (int t = 0; t < 5; t++) a += sc[SW1 + t * 20 + co] * dif[row + t];
            int p = g0 + row - 6;
            float v = elu1(a);
            if (row < 2 || row >= 190 || p < 0 || p >= N) v = 0.f;
            bA[row * 88 + co] = __float2half_rn(v);
        }
        __syncthreads();

        // L2: 20->40 k5 pad2 | taps5 kc2 NT5 KP40 NR40, rows [4,188)
        mma_layer<5, 2, 2, 5, 40, 40, PW2, SB2, 4, 188>(smb, BA, 176, BB, 112, sc, warp, lane, g0, N);
        __syncthreads();

        // ---- prefetch next tile's uu (registers only; covered by L3/L4/L5 latency) ----
        {
            int tn = tile + GRID_P;
            if (tid < 196 && tn < nTiles) {
                int gd = tn * T + tid - 8;
                int i0 = min(max(gd - 1, 0), N - 1);
                int i1 = min(max(gd + 1, 0), N - 1);
                pf0 = __ldg(&uu[i0]);
                pf1 = __ldg(&uu[i1]);
            }
        }

        // L3: 40->80 k1 | kc3 NT10 KP56, rows [4,188)
        mma_layer<1, 0, 3, 10, 56, 80, PW3, SB3, 4, 188>(smb, BB, 112, BA, 176, sc, warp, lane, g0, N);
        __syncthreads();
        // L4: 80->40 k1 | kc5 NT5 KP84, rows [4,188)
        mma_layer<1, 0, 5, 5, 84, 40, PW4, SB4, 4, 188>(smb, BA, 176, BB, 112, sc, warp, lane, g0, N);
        __syncthreads();
        // L5+L6 fused: no stores, no trailing barrier (next dif barrier orders BB reuse)
        mma_layer5_l6(smb, BB, sc, warp, lane, g0, N);
    }
}

// ---------------- WENO reconstruction ----------------
__device__ __forceinline__ float weno_flux(float a, float b, float c, float d, float e,
                                           float bm_m1, float bm_0, float bm_p1)
{
    const float C1312 = 13.0f / 12.0f;
    const float E = 1e-13f;
    float f0 = (11.0f * c - 7.0f * d + 2.0f * e) * (1.0f / 6.0f);
    float f1 = (2.0f * b + 5.0f * c - d) * (1.0f / 6.0f);
    float f2 = (-a + 5.0f * b + 2.0f * c) * (1.0f / 6.0f);

    float t0a = c - 2.0f * d + e, t0b = 3.0f * c - 4.0f * d + e;
    float t1a = b - 2.0f * c + d, t1b = b - d;
    float t2a = a - 2.0f * b + c, t2b = a - 4.0f * b + 3.0f * c;
    float b0 = C1312 * t0a * t0a + 0.25f * t0b * t0b;
    float b1 = C1312 * t1a * t1a + 0.25f * t1b * t1b;
    float b2 = C1312 * t2a * t2a + 0.25f * t2b * t2b;

    b0 *= bm_p1;
    b1 *= bm_0;
    b2 *= bm_m1;

    float brs = (b2 - b0) * (b2 - b0);
    float e0 = (E + b0) * (E + b0);
    float e1 = (E + b1) * (E + b1);
    float e2 = (E + b2) * (E + b2);
    float om0 = 0.1f / e0 * (brs + e0);
    float om1 = 0.6f / e1 * (brs + e1);
    float om2 = 0.3f / e2 * (brs + e2);
    return (om0 * f0 + om1 * f1 + om2 * f2) / (om0 + om1 + om2);
}

__global__ void weno_kernel(const float* __restrict__ uu, float* __restrict__ out, int N)
{
    int i = blockIdx.x * blockDim.x + threadIdx.x;
    if (i >= N) return;
    int im2 = i - 2, im1 = i - 1, ip1 = i + 1, ip2 = i + 2, ip3 = i + 3;
    if (im2 < 0) im2 += N;
    if (im1 < 0) im1 += N;
    if (ip1 >= N) ip1 -= N;
    if (ip2 >= N) ip2 -= N;
    if (ip3 >= N) ip3 -= N;

    float umm = __ldg(&uu[im2]), um = __ldg(&uu[im1]), u0 = __ldg(&uu[i]);
    float up  = __ldg(&uu[ip1]), upp = __ldg(&uu[ip2]), uppp = __ldg(&uu[ip3]);
    float bm_m1 = g_bm[im1], bm_0 = g_bm[i], bm_p1 = g_bm[ip1];

    float fluxp = weno_flux(um, u0, up, upp, uppp, bm_m1, bm_0, bm_p1);
    float fluxn = weno_flux(umm, um, u0, up, upp, bm_m1, bm_0, bm_p1);

    out[i] = fluxp - fluxn;
}

extern "C" void kernel_launch(void* const* d_in, const int* in_sizes, int n_in,
                              void* d_out, int out_size)
{
    const float* uu = (const float*)d_in[0];
    const float* w1 = (const float*)d_in[1];
    const float* b1 = (const float*)d_in[2];
    const float* w2 = (const float*)d_in[3];
    const float* b2 = (const float*)d_in[4];
    const float* w3 = (const float*)d_in[5];
    const float* b3 = (const float*)d_in[6];
    const float* w4 = (const float*)d_in[7];
    const float* b4 = (const float*)d_in[8];
    const float* w5 = (const float*)d_in[9];
    const float* b5 = (const float*)d_in[10];
    const float* w6 = (const float*)d_in[11];
    const float* b6 = (const float*)d_in[12];
    float* out = (float*)d_out;
    int N = in_sizes[0];

    cudaFuncSetAttribute(cnn_kernel, cudaFuncAttributeMaxDynamicSharedMemorySize, SMEM_BYTES);

    int nTiles = (N + T - 1) / T;
    int grid = nTiles < GRID_P ? nTiles : GRID_P;
    cnn_kernel<<<grid, NTHREADS, SMEM_BYTES>>>(uu, w1, b1, w2, b2, w3, b3, w4, b4,
                                               w5, b5, w6, b6, N, nTiles);
    weno_kernel<<<(N + 255) / 256, 256>>>(uu, out, N);
}